// round 12
// baseline (speedup 1.0000x reference)
#include <cuda_runtime.h>
#include <cuda_bf16.h>
#include <math.h>

// ---------------------------------------------------------------------------
// TCAMSeeder exact port. R11: no logf in the streaming pass — candidates are
// recorded as (fmono(u), pix); top-k by Gumbel score computed sparsely using
// the provable bound s = log(p)+g(u) <= g(u) with runtime-verified u-tiers.
// side convention: 0 = fg, 1 = bg.
// ---------------------------------------------------------------------------

#define BN    64
#define HN    512
#define WN    512
#define HWN   262144
#define NBGC  78643
#define CAPP  16384
#define CAPC  79872

#define UCUT0 0xBF7C0000u   // fmono(0.984375f)  (63/64)
#define UCUT1 0xBF400000u   // fmono(0.75f)

typedef unsigned long long ull;
typedef unsigned int       u32;
typedef unsigned char      u8;

// ------------------------------ device scratch ------------------------------
__device__ ull g_pre[BN][HN * 8];
__device__ ull g_er [BN][HN * 8];
__device__ u32 g_ch_all[BN][64];
__device__ u32 g_ch_roi[BN][64];
__device__ u32 g_minb[BN], g_maxb[BN];
__device__ int g_nfg[BN], g_deg[BN];
__device__ int g_BbC[BN], g_needB[BN];
__device__ int g_BfC[BN], g_needF[BN];
__device__ int g_done1[BN], g_done2[BN];
__device__ ull g_rec[2][BN][CAPC];    // candidate records (fmono(u)<<32)|pix
__device__ int g_n[2][BN];
__device__ ull g_p1[2][BN][CAPP];     // stage-1 boundary value keys
__device__ ull g_pr[2][BN][CAPP];     // matching records
__device__ int g_np[2][BN];
__device__ ull g_sk[2][BN][CAPC];     // score keys scratch (top-k kernel)
__device__ ull g_seed[2][BN][HN * 8];

// ------------------------------ helpers ------------------------------
__device__ __forceinline__ int cbin(float v) {
    int k = (int)(v * 64.0f);
    return k > 63 ? 63 : k;
}
__device__ __forceinline__ u32 fmono(float f) {
    u32 b = __float_as_uint(f);
    return (b & 0x80000000u) ? ~b : (b | 0x80000000u);
}
__device__ __forceinline__ float fmono_inv(u32 m) {
    u32 b = (m & 0x80000000u) ? (m ^ 0x80000000u) : ~m;
    return __uint_as_float(b);
}
__device__ __forceinline__ void mark_seed(ull* seedimg, int pix) {
    atomicOr(&seedimg[(pix >> 9) * 8 + ((pix & 511) >> 6)], 1ull << (pix & 63));
}

// exact m-th largest 64-bit key among list[0..cnt) (block-collective)
__device__ __forceinline__ ull radix_kth_largest(const ull* __restrict__ list,
                                                 int cnt, int need) {
    __shared__ u32 rh[256];
    __shared__ ull s_pref;
    __shared__ int s_nd;
    int tid = threadIdx.x;
    if (tid == 0) { s_pref = 0ull; s_nd = need; }
    __syncthreads();
    for (int by = 7; by >= 0; --by) {
        for (int j = tid; j < 256; j += blockDim.x) rh[j] = 0;
        __syncthreads();
        ull mask = (by == 7) ? 0ull : (~0ull << (8 * (by + 1)));
        ull pref = s_pref;
        for (int i = tid; i < cnt; i += blockDim.x) {
            ull k = list[i];
            if (((k ^ pref) & mask) == 0ull)
                atomicAdd(&rh[(int)((k >> (8 * by)) & 255ull)], 1u);
        }
        __syncthreads();
        if (tid == 0) {
            int nd = s_nd; int cum = 0; int sel = 0;
            for (int v = 255; v >= 0; --v) {
                u32 c = rh[v];
                if (cum + (int)c >= nd) { sel = v; s_nd = nd - cum; break; }
                cum += c;
            }
            s_pref = pref | (((ull)sel) << (8 * by));
        }
        __syncthreads();
    }
    return s_pref;
}

// ------------------------------ kernels ------------------------------

__global__ void k_zero() {
    int i = blockIdx.x * blockDim.x + threadIdx.x;
    int stride = gridDim.x * blockDim.x;
    ull* seeds = &g_seed[0][0][0];
    for (int j = i; j < 2 * BN * HN * 8; j += stride) seeds[j] = 0ull;
    u32* h1 = &g_ch_all[0][0];
    u32* h2 = &g_ch_roi[0][0];
    for (int j = i; j < BN * 64; j += stride) { h1[j] = 0; h2[j] = 0; }
    if (i < BN) {
        g_n[0][i] = 0;  g_n[1][i] = 0;
        g_np[0][i] = 0; g_np[1][i] = 0;
        g_done1[i] = 0; g_done2[i] = 0;
        g_minb[i] = 0xFFFFFFFFu; g_maxb[i] = 0u;
    }
}

// P1: x -> pre-erosion bitmap, minmax, all-pixel 64-bin value hist; last block
// per image computes deg + bg coarse boundary.
__global__ void __launch_bounds__(256) k_prep(const float* __restrict__ x,
                                              const float* __restrict__ rt) {
    __shared__ u8 sc[256 * 68];
    __shared__ u32 smn[8], smx[8];
    int b = blockIdx.x >> 4;
    int chunk = blockIdx.x & 15;
    int tid = threadIdx.x, lane = tid & 31;
    for (int j = tid; j < 256 * 68 / 4; j += 256) ((u32*)sc)[j] = 0;
    float th = rt[b];
    float thA = (th == 0.0f) ? 1.0f : ((th == 255.0f) ? 254.0f : th);
    u32 mn = 0xFFFFFFFFu, mx = 0u;
    const float4* xb4 = (const float4*)(x + (size_t)b * HWN);
    u32* bm = (u32*)g_pre[b];
    int base = chunk * 4096;
    __syncthreads();
    for (int it = 0; it < 16; it++) {
        int gf4 = base + it * 256 + tid;
        float4 xv = xb4[gf4];
        float e[4] = {xv.x, xv.y, xv.z, xv.w};
        u32 nib = 0;
#pragma unroll
        for (int k = 0; k < 4; k++) {
            float cam = e[k];
            u32 cb2 = __float_as_uint(cam);
            mn = min(mn, cb2); mx = max(mx, cb2);
            sc[tid * 68 + cbin(cam + 1e-8f)]++;
            if (floorf(cam * 255.0f) > thA) nib |= (1u << k);
        }
        u32 vv = nib << (4 * (lane & 7));
        vv |= __shfl_xor_sync(0xFFFFFFFFu, vv, 1);
        vv |= __shfl_xor_sync(0xFFFFFFFFu, vv, 2);
        vv |= __shfl_xor_sync(0xFFFFFFFFu, vv, 4);
        if ((lane & 7) == 0) bm[gf4 >> 3] = vv;
    }
    __syncthreads();
    if (tid < 64) {
        u32 s = 0;
        for (int t2 = 0; t2 < 256; t2++) s += sc[t2 * 68 + tid];
        if (s) atomicAdd(&g_ch_all[b][tid], s);
    }
    for (int o = 16; o; o >>= 1) {
        mn = min(mn, __shfl_down_sync(0xFFFFFFFFu, mn, o));
        mx = max(mx, __shfl_down_sync(0xFFFFFFFFu, mx, o));
    }
    if (lane == 0) { smn[tid >> 5] = mn; smx[tid >> 5] = mx; }
    __syncthreads();
    if (tid == 0) {
        for (int w = 1; w < 8; w++) { mn = min(mn, smn[w]); mx = max(mx, smx[w]); }
        atomicMin(&g_minb[b], mn);
        atomicMax(&g_maxb[b], mx);
        __threadfence();
        int d = atomicAdd(&g_done1[b], 1);
        if (d == 15) {
            u32 mnv = atomicMin(&g_minb[b], 0xFFFFFFFFu);
            u32 mxv = atomicMax(&g_maxb[b], 0u);
            g_deg[b] = (mnv == mxv) ? 1 : 0;
            int cum = 0, Bb = 64, nd = 0;
            for (int j = 0; j < 64; j++) {
                int c = (int)atomicAdd(&g_ch_all[b][j], 0u);
                if (cum + c >= NBGC) { Bb = j; nd = NBGC - cum; break; }
                cum += c;
            }
            g_BbC[b] = Bb; g_needB[b] = nd;
        }
    }
}

// P2: 11x11 erosion (bit-packed, OOB=1) + roi popcount -> n_fg
__global__ void __launch_bounds__(1024) k_erode() {
    extern __shared__ ull dsm[];
    ull* s_pre = dsm;          // 4096
    ull* s_hb  = dsm + 4096;   // 4096
    __shared__ int red[32];
    int b = blockIdx.x, tid = threadIdx.x, lane = tid & 31;
    for (int i = tid; i < 4096; i += 1024) s_pre[i] = g_pre[b][i];
    __syncthreads();
    for (int i = tid; i < 4096; i += 1024) {
        int w = i & 7;
        ull av = s_pre[i];
        ull lo = w ? s_pre[i - 1] : ~0ull;
        ull hi = (w < 7) ? s_pre[i + 1] : ~0ull;
        ull r = av;
#pragma unroll
        for (int d = 1; d <= 5; d++)
            r &= ((av >> d) | (hi << (64 - d))) & ((av << d) | (lo >> (64 - d)));
        s_hb[i] = r;
    }
    __syncthreads();
    int pc = 0;
    for (int i = tid; i < 4096; i += 1024) {
        int row = i >> 3, w = i & 7;
        ull r = ~0ull;
#pragma unroll
        for (int d = -5; d <= 5; d++) {
            int rr = row + d;
            if (rr >= 0 && rr < HN) r &= s_hb[rr * 8 + w];
        }
        g_er[b][i] = r;
        pc += __popcll(r);
    }
    for (int o = 16; o; o >>= 1) pc += __shfl_down_sync(0xFFFFFFFFu, pc, o);
    if (lane == 0) red[tid >> 5] = pc;
    __syncthreads();
    if (tid == 0) {
        int c = 0;
        for (int w = 0; w < 32; w++) c += red[w];
        g_nfg[b] = (int)floorf(0.3f * (float)c);
    }
}

// P3: roi 64-bin value hist (skipped when n_fg==0); last block: fg boundary
__global__ void __launch_bounds__(256) k_roihist(const float* __restrict__ x) {
    __shared__ u8 sc[256 * 68];
    int b = blockIdx.x >> 4;
    int chunk = blockIdx.x & 15;
    int tid = threadIdx.x;
    int nfg = g_nfg[b];
    if (nfg > 0) {
        for (int j = tid; j < 256 * 68 / 4; j += 256) ((u32*)sc)[j] = 0;
        __syncthreads();
        const float4* xb4 = (const float4*)(x + (size_t)b * HWN);
        const u32* erw = (const u32*)g_er[b];
        int base = chunk * 4096;
        for (int it = 0; it < 16; it++) {
            int gf4 = base + it * 256 + tid;
            u32 rbits = (erw[gf4 >> 3] >> ((gf4 & 7) * 4)) & 0xFu;
            if (rbits) {
                float4 xv = xb4[gf4];
                if (rbits & 1u) sc[tid * 68 + cbin(xv.x + 1e-8f)]++;
                if (rbits & 2u) sc[tid * 68 + cbin(xv.y + 1e-8f)]++;
                if (rbits & 4u) sc[tid * 68 + cbin(xv.z + 1e-8f)]++;
                if (rbits & 8u) sc[tid * 68 + cbin(xv.w + 1e-8f)]++;
            }
        }
        __syncthreads();
        if (tid < 64) {
            u32 s = 0;
            for (int t2 = 0; t2 < 256; t2++) s += sc[t2 * 68 + tid];
            if (s) atomicAdd(&g_ch_roi[b][tid], s);
        }
        __syncthreads();
    }
    if (tid == 0) {
        __threadfence();
        int d = atomicAdd(&g_done2[b], 1);
        if (d == 15) {
            int n = g_nfg[b];
            int Bf = 64, nd = 0;
            if (n > 0) {
                int cum = 0;
                for (int j = 63; j >= 0; j--) {
                    int c = (int)atomicAdd(&g_ch_roi[b][j], 0u);
                    if (cum + c >= n) { Bf = j; nd = n - cum; break; }
                    cum += c;
                }
            }
            g_BfC[b] = Bf; g_needF[b] = nd;
        }
    }
}

// P4: streaming classify — emit candidate records + stage-1 boundary pairs.
// NO logf, NO shared memory, NO shfl-scan chains.
__global__ void __launch_bounds__(256) k_score(const float* __restrict__ x,
                                               const float* __restrict__ ufg,
                                               const float* __restrict__ ubg) {
    int b = blockIdx.x >> 4;
    int chunk = blockIdx.x & 15;
    int tid = threadIdx.x, lane = tid & 31;
    int BbC = g_BbC[b], BfC = g_BfC[b];
    const float4* xb4 = (const float4*)(x + (size_t)b * HWN);
    const float* ufp = ufg + (size_t)b * HWN;
    const float* ubp = ubg + (size_t)b * HWN;
    const u32* erw = (const u32*)g_er[b];
    int base = chunk * 4096;
    u32 lt = (1u << lane) - 1u;
    for (int it = 0; it < 16; it++) {
        int gf4 = base + it * 256 + tid;
        float4 xv = xb4[gf4];
        u32 rbits = (erw[gf4 >> 3] >> ((gf4 & 7) * 4)) & 0xFu;
        float vx[4] = {xv.x + 1e-8f, xv.y + 1e-8f, xv.z + 1e-8f, xv.w + 1e-8f};
        bool bs[4], bb[4], fs[4], fb[4];
        ull recB[4], recF[4], keyB[4], keyF[4];
#pragma unroll
        for (int k = 0; k < 4; k++) {
            float v = vx[k];
            int c = cbin(v);
            int pix = gf4 * 4 + k;
            int roi = (rbits >> k) & 1;
            bs[k] = c < BbC;  bb[k] = (c == BbC);
            fs[k] = roi && (c > BfC);  fb[k] = roi && (c == BfC);
            float uB = 0.0f, uF = 0.0f;
            if (bs[k] | bb[k]) uB = ubp[pix];
            if (fs[k] | fb[k]) uF = ufp[pix];
            recB[k] = (((ull)(__float_as_uint(uB) | 0x80000000u)) << 32) | (u32)pix;
            recF[k] = (((ull)(__float_as_uint(uF) | 0x80000000u)) << 32) | (u32)pix;
            u32 vb = __float_as_uint(v);
            keyB[k] = ~((((ull)vb) << 32) | (u32)pix);
            keyF[k] = (((ull)vb) << 32) | (u32)(HWN - 1 - pix);
        }
        // sure bg records
        {
            u32 m0 = __ballot_sync(~0u, bs[0]), m1 = __ballot_sync(~0u, bs[1]);
            u32 m2 = __ballot_sync(~0u, bs[2]), m3 = __ballot_sync(~0u, bs[3]);
            int p0 = __popc(m0), p01 = p0 + __popc(m1), p012 = p01 + __popc(m2);
            int tot = p012 + __popc(m3);
            int bse = 0;
            if (lane == 0 && tot) bse = atomicAdd(&g_n[1][b], tot);
            bse = __shfl_sync(~0u, bse, 0);
            if (bs[0]) { int j = bse + __popc(m0 & lt);        if (j < CAPC) g_rec[1][b][j] = recB[0]; }
            if (bs[1]) { int j = bse + p0 + __popc(m1 & lt);   if (j < CAPC) g_rec[1][b][j] = recB[1]; }
            if (bs[2]) { int j = bse + p01 + __popc(m2 & lt);  if (j < CAPC) g_rec[1][b][j] = recB[2]; }
            if (bs[3]) { int j = bse + p012 + __popc(m3 & lt); if (j < CAPC) g_rec[1][b][j] = recB[3]; }
        }
        // sure fg records
        {
            u32 m0 = __ballot_sync(~0u, fs[0]), m1 = __ballot_sync(~0u, fs[1]);
            u32 m2 = __ballot_sync(~0u, fs[2]), m3 = __ballot_sync(~0u, fs[3]);
            int p0 = __popc(m0), p01 = p0 + __popc(m1), p012 = p01 + __popc(m2);
            int tot = p012 + __popc(m3);
            int bse = 0;
            if (lane == 0 && tot) bse = atomicAdd(&g_n[0][b], tot);
            bse = __shfl_sync(~0u, bse, 0);
            if (fs[0]) { int j = bse + __popc(m0 & lt);        if (j < CAPC) g_rec[0][b][j] = recF[0]; }
            if (fs[1]) { int j = bse + p0 + __popc(m1 & lt);   if (j < CAPC) g_rec[0][b][j] = recF[1]; }
            if (fs[2]) { int j = bse + p01 + __popc(m2 & lt);  if (j < CAPC) g_rec[0][b][j] = recF[2]; }
            if (fs[3]) { int j = bse + p012 + __popc(m3 & lt); if (j < CAPC) g_rec[0][b][j] = recF[3]; }
        }
        // bg boundary pairs
        {
            u32 m0 = __ballot_sync(~0u, bb[0]), m1 = __ballot_sync(~0u, bb[1]);
            u32 m2 = __ballot_sync(~0u, bb[2]), m3 = __ballot_sync(~0u, bb[3]);
            int p0 = __popc(m0), p01 = p0 + __popc(m1), p012 = p01 + __popc(m2);
            int tot = p012 + __popc(m3);
            int bse = 0;
            if (lane == 0 && tot) bse = atomicAdd(&g_np[1][b], tot);
            bse = __shfl_sync(~0u, bse, 0);
            if (bb[0]) { int j = bse + __popc(m0 & lt);        if (j < CAPP) { g_p1[1][b][j] = keyB[0]; g_pr[1][b][j] = recB[0]; } }
            if (bb[1]) { int j = bse + p0 + __popc(m1 & lt);   if (j < CAPP) { g_p1[1][b][j] = keyB[1]; g_pr[1][b][j] = recB[1]; } }
            if (bb[2]) { int j = bse + p01 + __popc(m2 & lt);  if (j < CAPP) { g_p1[1][b][j] = keyB[2]; g_pr[1][b][j] = recB[2]; } }
            if (bb[3]) { int j = bse + p012 + __popc(m3 & lt); if (j < CAPP) { g_p1[1][b][j] = keyB[3]; g_pr[1][b][j] = recB[3]; } }
        }
        // fg boundary pairs
        {
            u32 m0 = __ballot_sync(~0u, fb[0]), m1 = __ballot_sync(~0u, fb[1]);
            u32 m2 = __ballot_sync(~0u, fb[2]), m3 = __ballot_sync(~0u, fb[3]);
            int p0 = __popc(m0), p01 = p0 + __popc(m1), p012 = p01 + __popc(m2);
            int tot = p012 + __popc(m3);
            int bse = 0;
            if (lane == 0 && tot) bse = atomicAdd(&g_np[0][b], tot);
            bse = __shfl_sync(~0u, bse, 0);
            if (fb[0]) { int j = bse + __popc(m0 & lt);        if (j < CAPP) { g_p1[0][b][j] = keyF[0]; g_pr[0][b][j] = recF[0]; } }
            if (fb[1]) { int j = bse + p0 + __popc(m1 & lt);   if (j < CAPP) { g_p1[0][b][j] = keyF[1]; g_pr[0][b][j] = recF[1]; } }
            if (fb[2]) { int j = bse + p01 + __popc(m2 & lt);  if (j < CAPP) { g_p1[0][b][j] = keyF[2]; g_pr[0][b][j] = recF[2]; } }
            if (fb[3]) { int j = bse + p012 + __popc(m3 & lt); if (j < CAPP) { g_p1[0][b][j] = keyF[3]; g_pr[0][b][j] = recF[3]; } }
        }
    }
}

// P5: stage-1 boundary refinement — append exact winners' records
__global__ void __launch_bounds__(256) k_refine1() {
    int b = blockIdx.x, side = blockIdx.y;
    int need = side ? g_needB[b] : g_needF[b];
    if (need <= 0) return;
    int cnt = g_np[side][b];
    if (cnt > CAPP) cnt = CAPP;
    ull T = radix_kth_largest(g_p1[side][b], cnt, need);
    for (int i = threadIdx.x; i < cnt; i += 256) {
        if (g_p1[side][b][i] >= T) {
            int pos = atomicAdd(&g_n[side][b], 1);
            if (pos < CAPC) g_rec[side][b][pos] = g_pr[side][b][i];
        }
    }
}

// P6: sparse exact top-K by Gumbel score with u-tier verification.
__global__ void __launch_bounds__(256) k_topk(const float* __restrict__ x) {
    __shared__ int s_cnt;
    __shared__ int s_done;
    int b = blockIdx.x, side = blockIdx.y;
    int K;
    if (side == 0) {
        int nf = g_nfg[b];
        K = g_deg[b] ? 0 : (nf < 100 ? nf : 100);
    } else {
        K = g_deg[b] ? 0 : 100;
    }
    if (K <= 0) return;
    int N = g_n[side][b];
    if (N > CAPC) N = CAPC;
    const ull* recs = g_rec[side][b];
    ull* sk = g_sk[side][b];
    const float* xb = x + (size_t)b * HWN;
    int tid = threadIdx.x;
    if (tid == 0) s_done = 0;
    __syncthreads();
    for (int tier = 0; tier < 3; tier++) {
        if (s_done) break;   // s_done only changes at barriers -> uniform
        u32 ucut = (tier == 0) ? UCUT0 : (tier == 1) ? UCUT1 : 0u;
        if (tid == 0) s_cnt = 0;
        __syncthreads();
        for (int i = tid; i < N; i += 256) {
            ull r = recs[i];
            u32 uhi = (u32)(r >> 32);
            if (uhi >= ucut) {
                float u = __uint_as_float(uhi & 0x7FFFFFFFu);
                int pix = (int)(r & 0xFFFFFFFFull);
                float v = xb[pix] + 1e-8f;
                float p = side ? (fmaxf(1.0f - v, 0.0f) + 1e-8f) : v;
                float s = logf(p) - logf(-logf(u));
                int pos = atomicAdd(&s_cnt, 1);
                sk[pos] = (((ull)fmono(s)) << 32) | (u32)(HWN - 1 - pix);
            }
        }
        __syncthreads();
        int cnt = s_cnt;
        bool ok = false;
        ull T = 0;
        if (cnt >= K) {
            T = radix_kth_largest(sk, cnt, K);
            if (tier == 2) ok = true;
            else {
                float sK = fmono_inv((u32)(T >> 32));
                float edge = (tier == 0) ? 0.984375f : 0.75f;
                float gc = -logf(-logf(edge));
                ok = (sK > gc);    // strict: excluded s <= g <= gc < sK
            }
        }
        if (ok) {
            ull* seed = g_seed[side][b];
            for (int i = tid; i < cnt; i += 256)
                if (sk[i] >= T) mark_seed(seed, HWN - 1 - (int)(sk[i] & 0xFFFFFFFFull));
            if (tid == 0) s_done = 1;
        }
        __syncthreads();
    }
}

// P7: 3x3 dilation + compose float32 output
__global__ void k_output(float* __restrict__ out) {
    __shared__ ull sv[2][8];
    __shared__ ull sh2[2][8];
    int t = blockIdx.x;
    int b = t >> 9;
    int row = t & 511;
    int c = threadIdx.x;
    if (c < 16) {
        int q = c >> 3, w = c & 7;
        const ull* seed = g_seed[q][b];
        ull v = seed[row * 8 + w];
        if (row > 0)      v |= seed[(row - 1) * 8 + w];
        if (row < HN - 1) v |= seed[(row + 1) * 8 + w];
        sv[q][w] = v;
    }
    __syncthreads();
    if (c < 16) {
        int q = c >> 3, w = c & 7;
        ull m = sv[q][w];
        ull hh = m | (m << 1) | (m >> 1);
        if (w > 0) hh |= sv[q][w - 1] >> 63;
        if (w < 7) hh |= sv[q][w + 1] << 63;
        sh2[q][w] = hh;
    }
    __syncthreads();
    int w = c >> 6, bit = c & 63;
    int f = (int)((sh2[0][w] >> bit) & 1ull);
    int g = (int)((sh2[1][w] >> bit) & 1ull);
    float val;
    if (f && !g)      val = 1.0f;
    else if (g && !f) val = 0.0f;
    else              val = -255.0f;
    out[(size_t)b * HWN + (size_t)row * WN + c] = val;
}

// ------------------------------ launch ------------------------------
extern "C" void kernel_launch(void* const* d_in, const int* in_sizes, int n_in,
                              void* d_out, int out_size) {
    (void)out_size;
    const float* big[3] = {nullptr, nullptr, nullptr};
    const float* rt = nullptr;
    int nb = 0;
    for (int i = 0; i < n_in && i < 4; i++) {
        if (in_sizes[i] == BN) rt = (const float*)d_in[i];
        else if (nb < 3)       big[nb++] = (const float*)d_in[i];
    }
    const float* x   = big[0];
    const float* ufg = big[1];
    const float* ubg = big[2];
    float* out = (float*)d_out;

    cudaFuncSetAttribute(k_erode, cudaFuncAttributeMaxDynamicSharedMemorySize, 65536);

    k_zero<<<512, 256>>>();
    k_prep<<<BN * 16, 256>>>(x, rt);
    k_erode<<<BN, 1024, 65536>>>();
    k_roihist<<<BN * 16, 256>>>(x);
    k_score<<<BN * 16, 256>>>(x, ufg, ubg);
    k_refine1<<<dim3(BN, 2), 256>>>();
    k_topk<<<dim3(BN, 2), 256>>>(x);
    k_output<<<BN * HN, 512>>>(out);
}